// round 17
// baseline (speedup 1.0000x reference)
#include <cuda_runtime.h>

// Winograd F(2x2,3x3) with constant Laplacian filter == direct 3x3 conv of each
// 4x4 tile; row-separable:
//   row r = (a,b,c,d):  x_r = (-b, -c),  y_r = (4b-a-c, 4c-b-d)
//   O_row0 = x_0 + y_1 + x_2 ;  O_row1 = x_1 + y_2 + x_3
//
// One lane per input row (float4, coalesced LDG.128); 4-lane groups assemble a
// tile via SHFL. ITERS=4 independent front-batched loads per segment (MLP=4),
// streaming cache hints. R16 change: PERSISTENT grid-stride launch — one
// resident wave (8 CTAs/SM) loops over segments, eliminating ~13 wave
// transitions and ragged per-wave tails of the 16384-CTA launch. Per-segment
// body is byte-identical to the replicated-best 49.6us config.

#define ITERS 4
#define TPB 256

__global__ __launch_bounds__(TPB) void winograd_kernel(
    const float4* __restrict__ in4,   // n4 float4s (4 per tile, row-major)
    float2* __restrict__ out2,        // 2 float2 per tile
    int n4)
{
    const unsigned FULL = 0xFFFFFFFFu;
    int tid = threadIdx.x;
    int r = tid & 3;
    int chunk = TPB * ITERS;                 // rows per segment
    int stride = gridDim.x * chunk;

    for (int seg = blockIdx.x * chunk; seg < n4; seg += stride) {
        float4 m[ITERS];
        int    j[ITERS];

        // Front-batch independent loads (MLP_p1 = ITERS)
        #pragma unroll
        for (int k = 0; k < ITERS; k++) {
            j[k] = seg + k * TPB + tid;
            m[k] = (j[k] < n4) ? __ldcs(&in4[j[k]])
                               : make_float4(0.f, 0.f, 0.f, 0.f);
        }

        #pragma unroll
        for (int k = 0; k < ITERS; k++) {
            float x0 = -m[k].y;
            float x1 = -m[k].z;
            float y0 = fmaf(4.0f, m[k].y, -m[k].x) - m[k].z;   // 4b - a - c
            float y1 = fmaf(4.0f, m[k].z, -m[k].y) - m[k].w;   // 4c - b - d

            float z0 = x0 + __shfl_down_sync(FULL, y0, 1);
            float z1 = x1 + __shfl_down_sync(FULL, y1, 1);
            float o0 = z0 + __shfl_down_sync(FULL, x0, 2);
            float o1 = z1 + __shfl_down_sync(FULL, x1, 2);

            if (r < 2 && j[k] < n4) {
                // tile = j>>2, output row r of that tile
                __stcs(&out2[((j[k] >> 2) << 1) | r], make_float2(o0, o1));
            }
        }
    }
}

extern "C" void kernel_launch(void* const* d_in, const int* in_sizes, int n_in,
                              void* d_out, int out_size) {
    const float* x = (const float*)d_in[0];
    float* out = (float*)d_out;
    int n4 = in_sizes[0] / 4;   // number of float4 rows (4 per tile)

    // One resident wave: regs=32 -> 8 CTAs of 256 threads per SM; GB300 has
    // 148-152 SMs. 152*8 = 1216 blocks (slight oversubscription on 148 is
    // harmless; work distributes via the stride loop).
    int blocks = 1216;
    int chunk = TPB * ITERS;
    int max_blocks = (n4 + chunk - 1) / chunk;
    if (blocks > max_blocks) blocks = max_blocks;

    winograd_kernel<<<blocks, TPB>>>(
        (const float4*)x, (float2*)out, n4);
}